// round 13
// baseline (speedup 1.0000x reference)
#include <cuda_runtime.h>
#include <cstdint>
#include <math.h>

#define B_ 2
#define S_ 2048
#define H_ 32
#define KV_ 8
#define D_ 128
#define T_ (B_*S_)                 // 4096
#define HID_ (H_*D_)               // 4096
#define OUTQKV_ ((H_+2*KV_)*D_)    // 6144

// ---------------- scratch (device globals; no allocation allowed) ----------------
__device__ int8_t g_x8[(size_t)T_*HID_];
__device__ int8_t g_wqkv8[(size_t)OUTQKV_*HID_];
__device__ int8_t g_wo8[(size_t)HID_*HID_];
__device__ float  g_qkv[(size_t)T_*OUTQKV_];
__device__ float  g_attn[(size_t)T_*HID_];
__device__ int8_t g_attnq[(size_t)T_*HID_];
__device__ float  g_ascale[T_];
__device__ float2 g_rope[S_*64];           // (cos,sin) per (pos, freq)

// ---------------- f32x2 packed math helpers ----------------
#define FMA2(d,a,b) asm("fma.rn.f32x2 %0, %1, %2, %0;" : "+l"(d) : "l"(a), "l"(b))
#define MUL2(d,a,b) asm("mul.rn.f32x2 %0, %1, %2;" : "=l"(d) : "l"(a), "l"(b))

__device__ __forceinline__ unsigned long long pk2(float lo, float hi) {
    unsigned long long r;
    asm("mov.b64 %0, {%1,%2};" : "=l"(r) : "f"(lo), "f"(hi));
    return r;
}
__device__ __forceinline__ void upk2(float& lo, float& hi, unsigned long long v) {
    asm("mov.b64 {%0,%1}, %2;" : "=f"(lo), "=f"(hi) : "l"(v));
}

// ---------------- cp.async helpers ----------------
__device__ __forceinline__ void cp16(void* dst, const void* src) {
    unsigned d = (unsigned)__cvta_generic_to_shared(dst);
    asm volatile("cp.async.cg.shared.global [%0], [%1], 16;" :: "r"(d), "l"(src) : "memory");
}
__device__ __forceinline__ void cp4(void* dst, const void* src) {
    unsigned d = (unsigned)__cvta_generic_to_shared(dst);
    asm volatile("cp.async.ca.shared.global [%0], [%1], 4;" :: "r"(d), "l"(src) : "memory");
}
#define CP_COMMIT() asm volatile("cp.async.commit_group;" ::: "memory")
#define CP_WAIT(n)  asm volatile("cp.async.wait_group %0;" :: "n"(n) : "memory")

// ---------------- int32 -> int8 pack ----------------
__global__ void pack_int8_kernel(const int* __restrict__ in, int8_t* __restrict__ out, int n4) {
    int i = blockIdx.x * blockDim.x + threadIdx.x;
    if (i >= n4) return;
    int4 v = ((const int4*)in)[i];
    ((char4*)out)[i] = make_char4((signed char)v.x, (signed char)v.y,
                                  (signed char)v.z, (signed char)v.w);
}

// ---------------- block-scaled s8 GEMM (unchanged: 88.8% tensor) ----------------
__device__ __forceinline__ void mma_s8(int c[4], const int a[4], const int b[2]) {
    asm volatile(
        "mma.sync.aligned.m16n8k32.row.col.s32.s8.s8.s32 "
        "{%0,%1,%2,%3}, {%4,%5,%6,%7}, {%8,%9}, {%0,%1,%2,%3};\n"
        : "+r"(c[0]), "+r"(c[1]), "+r"(c[2]), "+r"(c[3])
        : "r"(a[0]), "r"(a[1]), "r"(a[2]), "r"(a[3]), "r"(b[0]), "r"(b[1]));
}

#define GST2 27648                          // A(128*144) + B(64*144) per stage
#define GSMEM2 (2*GST2 + 2*64*4)            // + 2-stage col scales

__device__ __forceinline__ void gemm_load_stage(
    int8_t* dsm, const int8_t* A, const int8_t* Bm, const float* colscale,
    int bm0, int bn0, int K, int ng, int tid, int st, int grp)
{
    int8_t* sA = dsm + st * GST2;
    int8_t* sB = sA + 18432;
    float*  sS = (float*)(dsm + 2 * GST2) + st * 64;
    #pragma unroll
    for (int i = 0; i < 6; ++i) {
        int cidx = tid + i * 256;
        if (cidx < 1024) {
            int r = cidx >> 3, c = (cidx & 7) << 4;
            cp16(sA + r * 144 + c, A + (size_t)(bm0 + r) * K + (grp << 7) + c);
        } else {
            int j = cidx - 1024;
            int r = j >> 3, c = (j & 7) << 4;
            cp16(sB + r * 144 + c, Bm + (size_t)(bn0 + r) * K + (grp << 7) + c);
        }
    }
    if (tid < 64) cp4(sS + tid, colscale + (size_t)(bn0 + tid) * ng + grp);
}

__global__ __launch_bounds__(256, 2) void gemm_s8_kernel(
    const int8_t* __restrict__ A, const int8_t* __restrict__ Bm,
    const float* __restrict__ colscale, const float* __restrict__ rowscale,
    float* __restrict__ C, int M, int N, int K)
{
    extern __shared__ __align__(16) int8_t dsm[];

    const int tid  = threadIdx.x;
    const int warp = tid >> 5, lane = tid & 31;
    const int wm = warp & 3, wn = warp >> 2;
    const int g  = lane >> 2, tg = lane & 3;
    const int bm0 = blockIdx.y * 128, bn0 = blockIdx.x * 64;
    const int ng = K >> 7;

    float facc[2][4][4];
    #pragma unroll
    for (int mt = 0; mt < 2; ++mt)
        #pragma unroll
        for (int nt = 0; nt < 4; ++nt)
            #pragma unroll
            for (int e = 0; e < 4; ++e) facc[mt][nt][e] = 0.f;

    gemm_load_stage(dsm, A, Bm, colscale, bm0, bn0, K, ng, tid, 0, 0);
    CP_COMMIT();

    for (int grp = 0; grp < ng; ++grp) {
        const int st = grp & 1;
        if (grp + 1 < ng) {
            gemm_load_stage(dsm, A, Bm, colscale, bm0, bn0, K, ng, tid, st ^ 1, grp + 1);
            CP_COMMIT();
            CP_WAIT(1);
        } else {
            CP_WAIT(0);
        }
        __syncthreads();

        const int8_t* smA = dsm + st * GST2;
        const int8_t* smB = smA + 18432;
        const float*  sS  = (const float*)(dsm + 2 * GST2) + st * 64;

        int iacc[2][4][4];
        #pragma unroll
        for (int mt = 0; mt < 2; ++mt)
            #pragma unroll
            for (int nt = 0; nt < 4; ++nt)
                #pragma unroll
                for (int e = 0; e < 4; ++e) iacc[mt][nt][e] = 0;

        #pragma unroll
        for (int ks = 0; ks < 4; ++ks) {
            int a[2][4], b[4][2];
            #pragma unroll
            for (int mt = 0; mt < 2; ++mt) {
                const int8_t* p = smA + (wm * 32 + mt * 16 + g) * 144 + ks * 32 + tg * 4;
                a[mt][0] = *(const int*)(p);
                a[mt][1] = *(const int*)(p + 8 * 144);
                a[mt][2] = *(const int*)(p + 16);
                a[mt][3] = *(const int*)(p + 8 * 144 + 16);
            }
            #pragma unroll
            for (int nt = 0; nt < 4; ++nt) {
                const int8_t* p = smB + (wn * 32 + nt * 8 + g) * 144 + ks * 32 + tg * 4;
                b[nt][0] = *(const int*)(p);
                b[nt][1] = *(const int*)(p + 16);
            }
            #pragma unroll
            for (int mt = 0; mt < 2; ++mt)
                #pragma unroll
                for (int nt = 0; nt < 4; ++nt)
                    mma_s8(iacc[mt][nt], a[mt], b[nt]);
        }

        #pragma unroll
        for (int mt = 0; mt < 2; ++mt)
            #pragma unroll
            for (int nt = 0; nt < 4; ++nt) {
                int colb = wn * 32 + nt * 8 + tg * 2;
                float s0 = sS[colb], s1 = sS[colb + 1];
                facc[mt][nt][0] += (float)iacc[mt][nt][0] * s0;
                facc[mt][nt][1] += (float)iacc[mt][nt][1] * s1;
                facc[mt][nt][2] += (float)iacc[mt][nt][2] * s0;
                facc[mt][nt][3] += (float)iacc[mt][nt][3] * s1;
            }
        __syncthreads();
    }

    #pragma unroll
    for (int mt = 0; mt < 2; ++mt) {
        int r0 = bm0 + wm * 32 + mt * 16 + g;
        float rs0 = rowscale[r0], rs1 = rowscale[r0 + 8];
        #pragma unroll
        for (int nt = 0; nt < 4; ++nt) {
            int col = bn0 + wn * 32 + nt * 8 + tg * 2;
            *(float2*)(C + (size_t)r0 * N + col) =
                make_float2(facc[mt][nt][0] * rs0, facc[mt][nt][1] * rs0);
            *(float2*)(C + (size_t)(r0 + 8) * N + col) =
                make_float2(facc[mt][nt][2] * rs1, facc[mt][nt][3] * rs1);
        }
    }
}

// ---------------- RoPE table + apply ----------------
__global__ void rope_table_kernel(float2* __restrict__ tab) {
    int idx = blockIdx.x * 256 + threadIdx.x;
    if (idx >= S_ * 64) return;
    int s = idx >> 6, i = idx & 63;
    float inv = exp2f((float)i * -0.31143075889569023f);  // theta^(-i/64)
    float ang = (float)s * inv;
    float sn, c;
    sincosf(ang, &sn, &c);
    tab[idx] = make_float2(c, sn);
}

__global__ void rope_kernel(float* __restrict__ qkv, const float2* __restrict__ tab) {
    int idx = blockIdx.x * 256 + threadIdx.x;
    if (idx >= T_ * (H_ + KV_) * 64) return;
    int i  = idx & 63;
    int hh = (idx >> 6) % (H_ + KV_);
    int t  = idx / ((H_ + KV_) * 64);
    int s  = t & (S_ - 1);
    int col = (hh < H_) ? hh * D_ : HID_ + (hh - H_) * D_;
    float2 cs = tab[s * 64 + i];
    float* p = qkv + (size_t)t * OUTQKV_ + col;
    float x1 = p[i], x2 = p[i + 64];
    p[i]      = x1 * cs.x - x2 * cs.y;
    p[i + 64] = x2 * cs.x + x1 * cs.y;
}

// ---------------- warp-local split-D f32x2 causal flash attention ----------------
// 512 threads; thread t: query q = t>>2 (0..127), quarter qt = t&3 (32 dims).
// Lanes 4q..4q+3 share a warp -> cross-quarter score reduction via shfl_xor.
// k/v smem rows: 4 quarters x 36 floats (conflict-free); q in registers.
#define AQB 128
#define AKB 16
#define KSTG (AKB*144)         // 2304 floats per (k or v) per stage
#define ASTG (2*KSTG)          // 4608 floats per stage (k + v)
#define ATTN_SMEM_BYTES (2*ASTG*4)   // 36864 B

__global__ __launch_bounds__(512, 1) void attn_kernel(const float* __restrict__ qkv,
                                                      float* __restrict__ attn) {
    extern __shared__ float sm[];
    const int tid = threadIdx.x;
    const int q  = tid >> 2;
    const int qt = tid & 3;
    const int qb = (gridDim.x - 1) - blockIdx.x;   // heaviest first
    const int h = blockIdx.y, b = blockIdx.z;
    const int g = h >> 2;
    const int q0 = qb * AQB;
    const int qpos = q0 + q;
    const float scale = 0.08838834764831845f;
    const int nkb = (q0 + AQB) / AKB;

    // prefetch tile 0 into stage 0
    for (int i = tid; i < 1024; i += 512) {
        int arr = i >> 9, rem = i & 511;
        int r = rem >> 5, d4 = rem & 31;
        const float* src = qkv + (size_t)(b * S_ + r) * OUTQKV_
                         + HID_ + arr * (KV_ * D_) + g * D_ + d4 * 4;
        float* dst = sm + arr * KSTG + r * 144 + (d4 >> 3) * 36 + (d4 & 7) * 4;
        cp16(dst, src);
    }
    CP_COMMIT();

    // this thread's q quarter into registers (pre-scaled)
    unsigned long long q2[16];
    {
        const float* qp = qkv + (size_t)(b * S_ + qpos) * OUTQKV_ + h * D_ + qt * 32;
        #pragma unroll
        for (int i = 0; i < 8; ++i) {
            float4 v = *(const float4*)(qp + i * 4);
            q2[2*i]   = pk2(v.x * scale, v.y * scale);
            q2[2*i+1] = pk2(v.z * scale, v.w * scale);
        }
    }

    unsigned long long o2[16];
    #pragma unroll
    for (int i = 0; i < 16; ++i) o2[i] = 0ull;
    float m = -1e30f, l = 0.f;

    for (int kb = 0; kb < nkb; ++kb) {
        const int st = kb & 1;
        CP_WAIT(0);
        __syncthreads();                       // tile st ready; st^1 consumed

        if (kb + 1 < nkb) {                    // prefetch next tile
            for (int i = tid; i < 1024; i += 512) {
                int arr = i >> 9, rem = i & 511;
                int r = rem >> 5, d4 = rem & 31;
                const float* src = qkv + (size_t)(b * S_ + (kb + 1) * AKB + r) * OUTQKV_
                                 + HID_ + arr * (KV_ * D_) + g * D_ + d4 * 4;
                float* dst = sm + (st ^ 1) * ASTG + arr * KSTG + r * 144 + (d4 >> 3) * 36 + (d4 & 7) * 4;
                cp16(dst, src);
            }
        }
        CP_COMMIT();

        const float* kq = sm + st * ASTG + qt * 36;
        const float* vq = sm + st * ASTG + KSTG + qt * 36;

        // ---- QK over this thread's 32 dims ----
        float s[AKB];
        #pragma unroll
        for (int j = 0; j < AKB; ++j) {
            unsigned long long s2 = 0ull;
            const float* kr = kq + j * 144;
            #pragma unroll
            for (int dg = 0; dg < 8; ++dg) {
                double2 kd = *(const double2*)(kr + dg * 4);
                FMA2(s2, q2[2*dg],   __double_as_longlong(kd.x));
                FMA2(s2, q2[2*dg+1], __double_as_longlong(kd.y));
            }
            float lo, hi; upk2(lo, hi, s2);
            s[j] = lo + hi;
        }

        // ---- cross-quarter reduction: lanes 4q..4q+3 ----
        #pragma unroll
        for (int j = 0; j < AKB; ++j) {
            s[j] += __shfl_xor_sync(0xffffffffu, s[j], 1);
            s[j] += __shfl_xor_sync(0xffffffffu, s[j], 2);
        }

        // ---- softmax (redundant across the 4 quarter-lanes) ----
        const int kbase = kb * AKB;
        #pragma unroll
        for (int j = 0; j < AKB; ++j)
            if (kbase + j > qpos) s[j] = -1e30f;
        float mn = m;
        #pragma unroll
        for (int j = 0; j < AKB; ++j) mn = fmaxf(mn, s[j]);
        float alpha = __expf(m - mn);
        m = mn;
        float ps = 0.f;
        #pragma unroll
        for (int j = 0; j < AKB; ++j) { s[j] = __expf(s[j] - mn); ps += s[j]; }
        l = l * alpha + ps;

        // ---- rescale + PV over this thread's 32 dims ----
        unsigned long long a2 = pk2(alpha, alpha);
        #pragma unroll
        for (int i = 0; i < 16; ++i) MUL2(o2[i], o2[i], a2);

        #pragma unroll
        for (int j = 0; j < AKB; ++j) {
            unsigned long long p2 = pk2(s[j], s[j]);
            const float* vr = vq + j * 144;
            #pragma unroll
            for (int dg = 0; dg < 8; ++dg) {
                double2 vd = *(const double2*)(vr + dg * 4);
                FMA2(o2[2*dg],   p2, __double_as_longlong(vd.x));
                FMA2(o2[2*dg+1], p2, __double_as_longlong(vd.y));
            }
        }
    }

    float invl = 1.0f / l;
    float* op = attn + (size_t)(b * S_ + qpos) * HID_ + h * D_ + qt * 32;
    #pragma unroll
    for (int i = 0; i < 8; ++i) {
        float lo0, hi0, lo1, hi1;
        upk2(lo0, hi0, o2[2*i]);
        upk2(lo1, hi1, o2[2*i+1]);
        *(float4*)(op + i * 4) = make_float4(lo0 * invl, hi0 * invl, lo1 * invl, hi1 * invl);
    }
}

// ---------------- per-token amax quantization ----------------
__device__ __forceinline__ signed char quant1(float x, float s) {
    float r = rintf(x / s);
    r = fminf(fmaxf(r, -127.f), 127.f);
    return (signed char)(int)r;
}

__global__ __launch_bounds__(256) void quant_kernel(const float* __restrict__ attn,
                                                    int8_t* __restrict__ q8,
                                                    float* __restrict__ ascale) {
    const int t = blockIdx.x, tid = threadIdx.x;
    const float4* row = (const float4*)(attn + (size_t)t * HID_);
    float4 v0 = row[tid], v1 = row[tid + 256], v2 = row[tid + 512], v3 = row[tid + 768];
    float mx = 0.f;
    mx = fmaxf(mx, fmaxf(fmaxf(fabsf(v0.x), fabsf(v0.y)), fmaxf(fabsf(v0.z), fabsf(v0.w))));
    mx = fmaxf(mx, fmaxf(fmaxf(fabsf(v1.x), fabsf(v1.y)), fmaxf(fabsf(v1.z), fabsf(v1.w))));
    mx = fmaxf(mx, fmaxf(fmaxf(fabsf(v2.x), fabsf(v2.y)), fmaxf(fabsf(v2.z), fabsf(v2.w))));
    mx = fmaxf(mx, fmaxf(fmaxf(fabsf(v3.x), fabsf(v3.y)), fmaxf(fabsf(v3.z), fabsf(v3.w))));
    #pragma unroll
    for (int off = 16; off; off >>= 1) mx = fmaxf(mx, __shfl_xor_sync(0xffffffffu, mx, off));
    __shared__ float red[8];
    if ((tid & 31) == 0) red[tid >> 5] = mx;
    __syncthreads();
    if (tid == 0) {
        float mm = red[0];
        #pragma unroll
        for (int i = 1; i < 8; ++i) mm = fmaxf(mm, red[i]);
        red[0] = fmaxf(mm, 1e-6f);
    }
    __syncthreads();
    float s = red[0] / 127.0f;
    if (tid == 0) ascale[t] = s;
    char4* outp = (char4*)(q8 + (size_t)t * HID_);
    outp[tid]       = make_char4(quant1(v0.x, s), quant1(v0.y, s), quant1(v0.z, s), quant1(v0.w, s));
    outp[tid + 256] = make_char4(quant1(v1.x, s), quant1(v1.y, s), quant1(v1.z, s), quant1(v1.w, s));
    outp[tid + 512] = make_char4(quant1(v2.x, s), quant1(v2.y, s), quant1(v2.z, s), quant1(v2.w, s));
    outp[tid + 768] = make_char4(quant1(v3.x, s), quant1(v3.y, s), quant1(v3.z, s), quant1(v3.w, s));
}

// ---------------- launch ----------------
extern "C" void kernel_launch(void* const* d_in, const int* in_sizes, int n_in,
                              void* d_out, int out_size) {
    (void)in_sizes; (void)n_in; (void)out_size;
    const int*   q_hidden = (const int*)d_in[0];
    const float* q_scale  = (const float*)d_in[1];
    const int*   w_qkv    = (const int*)d_in[3];
    const float* s_qkv    = (const float*)d_in[4];
    const int*   w_o      = (const int*)d_in[5];
    const float* s_o      = (const float*)d_in[6];
    float* out = (float*)d_out;

    int8_t *x8, *wq8, *wo8, *aq8;
    float *qkv, *attn, *ascale;
    float2* rtab;
    cudaGetSymbolAddress((void**)&x8,     g_x8);
    cudaGetSymbolAddress((void**)&wq8,    g_wqkv8);
    cudaGetSymbolAddress((void**)&wo8,    g_wo8);
    cudaGetSymbolAddress((void**)&aq8,    g_attnq);
    cudaGetSymbolAddress((void**)&qkv,    g_qkv);
    cudaGetSymbolAddress((void**)&attn,   g_attn);
    cudaGetSymbolAddress((void**)&ascale, g_ascale);
    cudaGetSymbolAddress((void**)&rtab,   g_rope);

    pack_int8_kernel<<<(T_*HID_/4 + 255) / 256, 256>>>(q_hidden, x8, T_*HID_/4);
    pack_int8_kernel<<<(OUTQKV_*HID_/4 + 255) / 256, 256>>>(w_qkv, wq8, OUTQKV_*HID_/4);
    pack_int8_kernel<<<(HID_*HID_/4 + 255) / 256, 256>>>(w_o, wo8, HID_*HID_/4);
    rope_table_kernel<<<(S_*64 + 255) / 256, 256>>>(rtab);

    cudaFuncSetAttribute(gemm_s8_kernel, cudaFuncAttributeMaxDynamicSharedMemorySize, GSMEM2);
    gemm_s8_kernel<<<dim3(OUTQKV_/64, T_/128), 256, GSMEM2>>>(
        x8, wq8, s_qkv, q_scale, qkv, T_, OUTQKV_, HID_);

    rope_kernel<<<(T_*(H_+KV_)*64 + 255) / 256, 256>>>(qkv, rtab);

    cudaFuncSetAttribute(attn_kernel, cudaFuncAttributeMaxDynamicSharedMemorySize, ATTN_SMEM_BYTES);
    attn_kernel<<<dim3(S_/AQB, H_, B_), 512, ATTN_SMEM_BYTES>>>(qkv, attn);

    quant_kernel<<<T_, 256>>>(attn, aq8, ascale);

    gemm_s8_kernel<<<dim3(HID_/64, T_/128), 256, GSMEM2>>>(
        aq8, wo8, s_o, ascale, out, T_, HID_, HID_);
}

// round 14
// speedup vs baseline: 1.3765x; 1.3765x over previous
#include <cuda_runtime.h>
#include <cstdint>
#include <math.h>

#define B_ 2
#define S_ 2048
#define H_ 32
#define KV_ 8
#define D_ 128
#define T_ (B_*S_)                 // 4096
#define HID_ (H_*D_)               // 4096
#define OUTQKV_ ((H_+2*KV_)*D_)    // 6144

// ---------------- scratch (device globals; no allocation allowed) ----------------
__device__ int8_t g_x8[(size_t)T_*HID_];
__device__ int8_t g_wqkv8[(size_t)OUTQKV_*HID_];
__device__ int8_t g_wo8[(size_t)HID_*HID_];
__device__ float  g_qkv[(size_t)T_*OUTQKV_];
__device__ float  g_attn[(size_t)T_*HID_];
__device__ int8_t g_attnq[(size_t)T_*HID_];
__device__ float  g_ascale[T_];
__device__ float2 g_rope[S_*64];           // (cos,sin) per (pos, freq)

// ---------------- f32x2 packed math helpers ----------------
#define FMA2(d,a,b) asm("fma.rn.f32x2 %0, %1, %2, %0;" : "+l"(d) : "l"(a), "l"(b))
#define MUL2(d,a,b) asm("mul.rn.f32x2 %0, %1, %2;" : "=l"(d) : "l"(a), "l"(b))

__device__ __forceinline__ unsigned long long pk2(float lo, float hi) {
    unsigned long long r;
    asm("mov.b64 %0, {%1,%2};" : "=l"(r) : "f"(lo), "f"(hi));
    return r;
}
__device__ __forceinline__ void upk2(float& lo, float& hi, unsigned long long v) {
    asm("mov.b64 {%0,%1}, %2;" : "=f"(lo), "=f"(hi) : "l"(v));
}

// ---------------- cp.async helpers ----------------
__device__ __forceinline__ void cp16(void* dst, const void* src) {
    unsigned d = (unsigned)__cvta_generic_to_shared(dst);
    asm volatile("cp.async.cg.shared.global [%0], [%1], 16;" :: "r"(d), "l"(src) : "memory");
}
__device__ __forceinline__ void cp4(void* dst, const void* src) {
    unsigned d = (unsigned)__cvta_generic_to_shared(dst);
    asm volatile("cp.async.ca.shared.global [%0], [%1], 4;" :: "r"(d), "l"(src) : "memory");
}
#define CP_COMMIT() asm volatile("cp.async.commit_group;" ::: "memory")
#define CP_WAIT(n)  asm volatile("cp.async.wait_group %0;" :: "n"(n) : "memory")

// ---------------- int32 -> int8 pack ----------------
__global__ void pack_int8_kernel(const int* __restrict__ in, int8_t* __restrict__ out, int n4) {
    int i = blockIdx.x * blockDim.x + threadIdx.x;
    if (i >= n4) return;
    int4 v = ((const int4*)in)[i];
    ((char4*)out)[i] = make_char4((signed char)v.x, (signed char)v.y,
                                  (signed char)v.z, (signed char)v.w);
}

// ---------------- block-scaled s8 GEMM (unchanged: 88.8% tensor) ----------------
__device__ __forceinline__ void mma_s8(int c[4], const int a[4], const int b[2]) {
    asm volatile(
        "mma.sync.aligned.m16n8k32.row.col.s32.s8.s8.s32 "
        "{%0,%1,%2,%3}, {%4,%5,%6,%7}, {%8,%9}, {%0,%1,%2,%3};\n"
        : "+r"(c[0]), "+r"(c[1]), "+r"(c[2]), "+r"(c[3])
        : "r"(a[0]), "r"(a[1]), "r"(a[2]), "r"(a[3]), "r"(b[0]), "r"(b[1]));
}

#define GST2 27648                          // A(128*144) + B(64*144) per stage
#define GSMEM2 (2*GST2 + 2*64*4)            // + 2-stage col scales

__device__ __forceinline__ void gemm_load_stage(
    int8_t* dsm, const int8_t* A, const int8_t* Bm, const float* colscale,
    int bm0, int bn0, int K, int ng, int tid, int st, int grp)
{
    int8_t* sA = dsm + st * GST2;
    int8_t* sB = sA + 18432;
    float*  sS = (float*)(dsm + 2 * GST2) + st * 64;
    #pragma unroll
    for (int i = 0; i < 6; ++i) {
        int cidx = tid + i * 256;
        if (cidx < 1024) {
            int r = cidx >> 3, c = (cidx & 7) << 4;
            cp16(sA + r * 144 + c, A + (size_t)(bm0 + r) * K + (grp << 7) + c);
        } else {
            int j = cidx - 1024;
            int r = j >> 3, c = (j & 7) << 4;
            cp16(sB + r * 144 + c, Bm + (size_t)(bn0 + r) * K + (grp << 7) + c);
        }
    }
    if (tid < 64) cp4(sS + tid, colscale + (size_t)(bn0 + tid) * ng + grp);
}

__global__ __launch_bounds__(256, 2) void gemm_s8_kernel(
    const int8_t* __restrict__ A, const int8_t* __restrict__ Bm,
    const float* __restrict__ colscale, const float* __restrict__ rowscale,
    float* __restrict__ C, int M, int N, int K)
{
    extern __shared__ __align__(16) int8_t dsm[];

    const int tid  = threadIdx.x;
    const int warp = tid >> 5, lane = tid & 31;
    const int wm = warp & 3, wn = warp >> 2;
    const int g  = lane >> 2, tg = lane & 3;
    const int bm0 = blockIdx.y * 128, bn0 = blockIdx.x * 64;
    const int ng = K >> 7;

    float facc[2][4][4];
    #pragma unroll
    for (int mt = 0; mt < 2; ++mt)
        #pragma unroll
        for (int nt = 0; nt < 4; ++nt)
            #pragma unroll
            for (int e = 0; e < 4; ++e) facc[mt][nt][e] = 0.f;

    gemm_load_stage(dsm, A, Bm, colscale, bm0, bn0, K, ng, tid, 0, 0);
    CP_COMMIT();

    for (int grp = 0; grp < ng; ++grp) {
        const int st = grp & 1;
        if (grp + 1 < ng) {
            gemm_load_stage(dsm, A, Bm, colscale, bm0, bn0, K, ng, tid, st ^ 1, grp + 1);
            CP_COMMIT();
            CP_WAIT(1);
        } else {
            CP_WAIT(0);
        }
        __syncthreads();

        const int8_t* smA = dsm + st * GST2;
        const int8_t* smB = smA + 18432;
        const float*  sS  = (const float*)(dsm + 2 * GST2) + st * 64;

        int iacc[2][4][4];
        #pragma unroll
        for (int mt = 0; mt < 2; ++mt)
            #pragma unroll
            for (int nt = 0; nt < 4; ++nt)
                #pragma unroll
                for (int e = 0; e < 4; ++e) iacc[mt][nt][e] = 0;

        #pragma unroll
        for (int ks = 0; ks < 4; ++ks) {
            int a[2][4], b[4][2];
            #pragma unroll
            for (int mt = 0; mt < 2; ++mt) {
                const int8_t* p = smA + (wm * 32 + mt * 16 + g) * 144 + ks * 32 + tg * 4;
                a[mt][0] = *(const int*)(p);
                a[mt][1] = *(const int*)(p + 8 * 144);
                a[mt][2] = *(const int*)(p + 16);
                a[mt][3] = *(const int*)(p + 8 * 144 + 16);
            }
            #pragma unroll
            for (int nt = 0; nt < 4; ++nt) {
                const int8_t* p = smB + (wn * 32 + nt * 8 + g) * 144 + ks * 32 + tg * 4;
                b[nt][0] = *(const int*)(p);
                b[nt][1] = *(const int*)(p + 16);
            }
            #pragma unroll
            for (int mt = 0; mt < 2; ++mt)
                #pragma unroll
                for (int nt = 0; nt < 4; ++nt)
                    mma_s8(iacc[mt][nt], a[mt], b[nt]);
        }

        #pragma unroll
        for (int mt = 0; mt < 2; ++mt)
            #pragma unroll
            for (int nt = 0; nt < 4; ++nt) {
                int colb = wn * 32 + nt * 8 + tg * 2;
                float s0 = sS[colb], s1 = sS[colb + 1];
                facc[mt][nt][0] += (float)iacc[mt][nt][0] * s0;
                facc[mt][nt][1] += (float)iacc[mt][nt][1] * s1;
                facc[mt][nt][2] += (float)iacc[mt][nt][2] * s0;
                facc[mt][nt][3] += (float)iacc[mt][nt][3] * s1;
            }
        __syncthreads();
    }

    #pragma unroll
    for (int mt = 0; mt < 2; ++mt) {
        int r0 = bm0 + wm * 32 + mt * 16 + g;
        float rs0 = rowscale[r0], rs1 = rowscale[r0 + 8];
        #pragma unroll
        for (int nt = 0; nt < 4; ++nt) {
            int col = bn0 + wn * 32 + nt * 8 + tg * 2;
            *(float2*)(C + (size_t)r0 * N + col) =
                make_float2(facc[mt][nt][0] * rs0, facc[mt][nt][1] * rs0);
            *(float2*)(C + (size_t)(r0 + 8) * N + col) =
                make_float2(facc[mt][nt][2] * rs1, facc[mt][nt][3] * rs1);
        }
    }
}

// ---------------- RoPE table + apply ----------------
__global__ void rope_table_kernel(float2* __restrict__ tab) {
    int idx = blockIdx.x * 256 + threadIdx.x;
    if (idx >= S_ * 64) return;
    int s = idx >> 6, i = idx & 63;
    float inv = exp2f((float)i * -0.31143075889569023f);  // theta^(-i/64)
    float ang = (float)s * inv;
    float sn, c;
    sincosf(ang, &sn, &c);
    tab[idx] = make_float2(c, sn);
}

__global__ void rope_kernel(float* __restrict__ qkv, const float2* __restrict__ tab) {
    int idx = blockIdx.x * 256 + threadIdx.x;
    if (idx >= T_ * (H_ + KV_) * 64) return;
    int i  = idx & 63;
    int hh = (idx >> 6) % (H_ + KV_);
    int t  = idx / ((H_ + KV_) * 64);
    int s  = t & (S_ - 1);
    int col = (hh < H_) ? hh * D_ : HID_ + (hh - H_) * D_;
    float2 cs = tab[s * 64 + i];
    float* p = qkv + (size_t)t * OUTQKV_ + col;
    float x1 = p[i], x2 = p[i + 64];
    p[i]      = x1 * cs.x - x2 * cs.y;
    p[i + 64] = x2 * cs.x + x1 * cs.y;
}

// ---------------- split-D f32x2 causal flash attention (symmetric softmax) ----------------
// 256 threads = 8 warps. Warps 0-3: dims [0,64); warps 4-7: dims [64,128).
// Both halves exchange score partials via per-half buffers, then each computes
// the full softmax redundantly with p[] staying in registers (1 fewer sync,
// no p/alpha roundtrips, no idle half).
#define QB 128
#define KB 32
#define QPAD 68
#define SSTR (2*KB*QPAD)   // one k (or v) stage: 4352 floats
// smem floats: q[2][QB][68] | k[2 st][..] | v[2 st][..] | part0[QB][33] | part1[QB][33]
#define ATTN_SMEM_FLOATS (2*QB*QPAD + 2*SSTR + 2*SSTR + 2*QB*33)

__global__ __launch_bounds__(256, 1) void attn_kernel(const float* __restrict__ qkv,
                                                      float* __restrict__ attn) {
    extern __shared__ float sm[];
    float* q_s   = sm;
    float* k_s   = q_s + 2 * QB * QPAD;     // [st][half][KB][QPAD]
    float* v_s   = k_s + 2 * SSTR;
    float* part0 = v_s + 2 * SSTR;          // written by half 0
    float* part1 = part0 + QB * 33;         // written by half 1

    const int tid = threadIdx.x;
    const int warp = tid >> 5, lane = tid & 31;
    const int half = warp >> 2;
    const int q = ((warp & 3) << 5) | lane;
    const int qb = (gridDim.x - 1) - blockIdx.x;   // heaviest blocks first
    const int h = blockIdx.y, b = blockIdx.z;
    const int g = h >> 2;
    const int q0 = qb * QB;
    const int qpos = q0 + q;
    const float scale = 0.08838834764831845f;
    const int nkb = (q0 + QB) / KB;

    float* part_my = half ? part1 : part0;
    const float* part_ot = half ? part0 : part1;

    // prefetch k/v tile 0 into stage 0
    for (int i = tid; i < KB * 32 * 2; i += 256) {
        int arr = i >> 10, rem = i & 1023;
        int r = rem >> 5, c = rem & 31;
        int hh = c >> 4, cc = c & 15;
        const float* src = qkv + (size_t)(b * S_ + r) * OUTQKV_
                         + HID_ + arr * (KV_ * D_) + g * D_ + c * 4;
        float* dst = (arr ? v_s : k_s) + hh * (KB * QPAD) + r * QPAD + cc * 4;
        cp16(dst, src);
    }
    CP_COMMIT();

    // load q block (scale-premultiplied), split by dim-half
    for (int i = tid; i < QB * 32; i += 256) {
        int r = i >> 5, c = i & 31;
        int hh = c >> 4, cc = c & 15;
        float4 v = *(const float4*)(qkv + (size_t)(b * S_ + q0 + r) * OUTQKV_ + h * D_ + c * 4);
        v.x *= scale; v.y *= scale; v.z *= scale; v.w *= scale;
        *(float4*)(q_s + hh * (QB * QPAD) + r * QPAD + cc * 4) = v;
    }

    unsigned long long o2[32];
    #pragma unroll
    for (int i = 0; i < 32; ++i) o2[i] = 0ull;
    float m = -1e30f, l = 0.f;

    const float* qrow = q_s + half * (QB * QPAD) + q * QPAD;

    for (int kb = 0; kb < nkb; ++kb) {
        const int st = kb & 1;
        CP_WAIT(0);
        __syncthreads();   // tile st ready; st^1 consumed; part reads of prev iter done

        if (kb + 1 < nkb) {   // prefetch next tile into st^1 during compute
            for (int i = tid; i < KB * 32 * 2; i += 256) {
                int arr = i >> 10, rem = i & 1023;
                int r = rem >> 5, c = rem & 31;
                int hh = c >> 4, cc = c & 15;
                const float* src = qkv + (size_t)(b * S_ + (kb + 1) * KB + r) * OUTQKV_
                                 + HID_ + arr * (KV_ * D_) + g * D_ + c * 4;
                float* dst = (arr ? v_s : k_s) + (st ^ 1) * SSTR + hh * (KB * QPAD) + r * QPAD + cc * 4;
                cp16(dst, src);
            }
        }
        CP_COMMIT();

        const float* kh = k_s + st * SSTR + half * (KB * QPAD);
        const float* vh = v_s + st * SSTR + half * (KB * QPAD);

        // ---- QK over this thread's 64 dims ----
        unsigned long long s2[32];
        #pragma unroll
        for (int j = 0; j < 32; ++j) s2[j] = 0ull;
        for (int dg = 0; dg < 16; ++dg) {
            double2 qd = *(const double2*)(qrow + dg * 4);
            unsigned long long q01 = __double_as_longlong(qd.x);
            unsigned long long q23 = __double_as_longlong(qd.y);
            #pragma unroll
            for (int j = 0; j < 32; ++j) {
                double2 kd = *(const double2*)(kh + j * QPAD + dg * 4);
                FMA2(s2[j], q01, __double_as_longlong(kd.x));
                FMA2(s2[j], q23, __double_as_longlong(kd.y));
            }
        }
        float s[32];
        #pragma unroll
        for (int j = 0; j < 32; ++j) { float lo, hi; upk2(lo, hi, s2[j]); s[j] = lo + hi; }

        // ---- symmetric partial exchange: each half writes its own buffer ----
        #pragma unroll
        for (int j = 0; j < 32; ++j) part_my[q * 33 + j] = s[j];
        __syncthreads();

        // ---- full softmax, redundantly in both halves (p stays in registers) ----
        const int kbase = kb * KB;
        #pragma unroll
        for (int j = 0; j < 32; ++j) {
            float t = s[j] + part_ot[q * 33 + j];
            s[j] = (kbase + j > qpos) ? -1e30f : t;
        }
        float mn = m;
        #pragma unroll
        for (int j = 0; j < 32; ++j) mn = fmaxf(mn, s[j]);
        float alpha = __expf(m - mn);
        m = mn;
        float ps = 0.f;
        #pragma unroll
        for (int j = 0; j < 32; ++j) { s[j] = __expf(s[j] - mn); ps += s[j]; }
        l = l * alpha + ps;

        // ---- rescale + PV over this thread's 64 dims ----
        unsigned long long a2 = pk2(alpha, alpha);
        #pragma unroll
        for (int i = 0; i < 32; ++i) MUL2(o2[i], o2[i], a2);

        #pragma unroll
        for (int j = 0; j < 32; ++j) {
            unsigned long long p2 = pk2(s[j], s[j]);
            const float* vr = vh + j * QPAD;
            #pragma unroll
            for (int dg = 0; dg < 16; ++dg) {
                double2 vd = *(const double2*)(vr + dg * 4);
                FMA2(o2[2 * dg],     p2, __double_as_longlong(vd.x));
                FMA2(o2[2 * dg + 1], p2, __double_as_longlong(vd.y));
            }
        }
    }

    float invl = 1.0f / l;   // l identical in both halves
    float* op = attn + (size_t)(b * S_ + qpos) * HID_ + h * D_ + half * 64;
    #pragma unroll
    for (int i = 0; i < 32; ++i) {
        float lo, hi; upk2(lo, hi, o2[i]);
        *(float2*)(op + i * 2) = make_float2(lo * invl, hi * invl);
    }
}

// ---------------- per-token amax quantization ----------------
__device__ __forceinline__ signed char quant1(float x, float s) {
    float r = rintf(x / s);
    r = fminf(fmaxf(r, -127.f), 127.f);
    return (signed char)(int)r;
}

__global__ __launch_bounds__(256) void quant_kernel(const float* __restrict__ attn,
                                                    int8_t* __restrict__ q8,
                                                    float* __restrict__ ascale) {
    const int t = blockIdx.x, tid = threadIdx.x;
    const float4* row = (const float4*)(attn + (size_t)t * HID_);
    float4 v0 = row[tid], v1 = row[tid + 256], v2 = row[tid + 512], v3 = row[tid + 768];
    float mx = 0.f;
    mx = fmaxf(mx, fmaxf(fmaxf(fabsf(v0.x), fabsf(v0.y)), fmaxf(fabsf(v0.z), fabsf(v0.w))));
    mx = fmaxf(mx, fmaxf(fmaxf(fabsf(v1.x), fabsf(v1.y)), fmaxf(fabsf(v1.z), fabsf(v1.w))));
    mx = fmaxf(mx, fmaxf(fmaxf(fabsf(v2.x), fabsf(v2.y)), fmaxf(fabsf(v2.z), fabsf(v2.w))));
    mx = fmaxf(mx, fmaxf(fmaxf(fabsf(v3.x), fabsf(v3.y)), fmaxf(fabsf(v3.z), fabsf(v3.w))));
    #pragma unroll
    for (int off = 16; off; off >>= 1) mx = fmaxf(mx, __shfl_xor_sync(0xffffffffu, mx, off));
    __shared__ float red[8];
    if ((tid & 31) == 0) red[tid >> 5] = mx;
    __syncthreads();
    if (tid == 0) {
        float mm = red[0];
        #pragma unroll
        for (int i = 1; i < 8; ++i) mm = fmaxf(mm, red[i]);
        red[0] = fmaxf(mm, 1e-6f);
    }
    __syncthreads();
    float s = red[0] / 127.0f;
    if (tid == 0) ascale[t] = s;
    char4* outp = (char4*)(q8 + (size_t)t * HID_);
    outp[tid]       = make_char4(quant1(v0.x, s), quant1(v0.y, s), quant1(v0.z, s), quant1(v0.w, s));
    outp[tid + 256] = make_char4(quant1(v1.x, s), quant1(v1.y, s), quant1(v1.z, s), quant1(v1.w, s));
    outp[tid + 512] = make_char4(quant1(v2.x, s), quant1(v2.y, s), quant1(v2.z, s), quant1(v2.w, s));
    outp[tid + 768] = make_char4(quant1(v3.x, s), quant1(v3.y, s), quant1(v3.z, s), quant1(v3.w, s));
}

// ---------------- launch ----------------
extern "C" void kernel_launch(void* const* d_in, const int* in_sizes, int n_in,
                              void* d_out, int out_size) {
    (void)in_sizes; (void)n_in; (void)out_size;
    const int*   q_hidden = (const int*)d_in[0];
    const float* q_scale  = (const float*)d_in[1];
    const int*   w_qkv    = (const int*)d_in[3];
    const float* s_qkv    = (const float*)d_in[4];
    const int*   w_o      = (const int*)d_in[5];
    const float* s_o      = (const float*)d_in[6];
    float* out = (float*)d_out;

    int8_t *x8, *wq8, *wo8, *aq8;
    float *qkv, *attn, *ascale;
    float2* rtab;
    cudaGetSymbolAddress((void**)&x8,     g_x8);
    cudaGetSymbolAddress((void**)&wq8,    g_wqkv8);
    cudaGetSymbolAddress((void**)&wo8,    g_wo8);
    cudaGetSymbolAddress((void**)&aq8,    g_attnq);
    cudaGetSymbolAddress((void**)&qkv,    g_qkv);
    cudaGetSymbolAddress((void**)&attn,   g_attn);
    cudaGetSymbolAddress((void**)&ascale, g_ascale);
    cudaGetSymbolAddress((void**)&rtab,   g_rope);

    pack_int8_kernel<<<(T_*HID_/4 + 255) / 256, 256>>>(q_hidden, x8, T_*HID_/4);
    pack_int8_kernel<<<(OUTQKV_*HID_/4 + 255) / 256, 256>>>(w_qkv, wq8, OUTQKV_*HID_/4);
    pack_int8_kernel<<<(HID_*HID_/4 + 255) / 256, 256>>>(w_o, wo8, HID_*HID_/4);
    rope_table_kernel<<<(S_*64 + 255) / 256, 256>>>(rtab);

    cudaFuncSetAttribute(gemm_s8_kernel, cudaFuncAttributeMaxDynamicSharedMemorySize, GSMEM2);
    gemm_s8_kernel<<<dim3(OUTQKV_/64, T_/128), 256, GSMEM2>>>(
        x8, wq8, s_qkv, q_scale, qkv, T_, OUTQKV_, HID_);

    rope_kernel<<<(T_*(H_+KV_)*64 + 255) / 256, 256>>>(qkv, rtab);

    const int attn_smem = ATTN_SMEM_FLOATS * sizeof(float);  // 173056 B
    cudaFuncSetAttribute(attn_kernel, cudaFuncAttributeMaxDynamicSharedMemorySize, attn_smem);
    attn_kernel<<<dim3(S_/QB, H_, B_), 256, attn_smem>>>(qkv, attn);

    quant_kernel<<<T_, 256>>>(attn, aq8, ascale);

    gemm_s8_kernel<<<dim3(HID_/64, T_/128), 256, GSMEM2>>>(
        aq8, wo8, s_o, ascale, out, T_, HID_, HID_);
}